// round 6
// baseline (speedup 1.0000x reference)
#include <cuda_runtime.h>

#define NODES 7
#define CH 256
#define HID 128
#define P_TOTAL 65536           // 16*64*64
#define P4 (P_TOTAL / 4)        // float4 granularity per channel plane
#define PF 4                    // prefetch depth (channels)

__device__ float g_nw[2 * NODES * CH];   // new_weight [b, n, c]
__device__ float g_n2[2 * NODES];        // n2 [b, n]

typedef unsigned long long ull;

// ---------------------------------------------------------------------------
// Packed f32x2 + wide memory helpers
// ---------------------------------------------------------------------------
__device__ __forceinline__ ull fma2(ull a, ull b, ull c) {
    ull d;
    asm("fma.rn.f32x2 %0, %1, %2, %3;" : "=l"(d) : "l"(a), "l"(b), "l"(c));
    return d;
}
__device__ __forceinline__ ull add2(ull a, ull b) {
    ull d;
    asm("add.rn.f32x2 %0, %1, %2;" : "=l"(d) : "l"(a), "l"(b));
    return d;
}
__device__ __forceinline__ ull pack2(float x, float y) {
    ull r;
    asm("mov.b64 %0, {%1, %2};" : "=l"(r) : "f"(x), "f"(y));
    return r;
}
__device__ __forceinline__ void unpack2(ull v, float& x, float& y) {
    asm("mov.b64 {%0, %1}, %2;" : "=f"(x), "=f"(y) : "l"(v));
}
__device__ __forceinline__ float4 ldcs128(const float4* p) {
    float4 v;
    asm volatile("ld.global.cs.v4.f32 {%0,%1,%2,%3}, [%4];"
                 : "=f"(v.x), "=f"(v.y), "=f"(v.z), "=f"(v.w) : "l"(p));
    return v;
}
__device__ __forceinline__ void stcs128(float4* p, float4 v) {
    asm volatile("st.global.cs.v4.f32 [%0], {%1,%2,%3,%4};"
                 :: "l"(p), "f"(v.x), "f"(v.y), "f"(v.z), "f"(v.w));
}

// ---------------------------------------------------------------------------
// Precompute: new_weight = inp @ weight [2,7,256], n2 = inp @ nfh [2,7]
// ---------------------------------------------------------------------------
__global__ void precompute_kernel(const float* __restrict__ inp,
                                  const float* __restrict__ nfh,
                                  const float* __restrict__ weight) {
    int bn = blockIdx.x;            // 0..13
    int c  = threadIdx.x;           // 0..255
    __shared__ float sh_inp[HID];
    if (c < HID) sh_inp[c] = inp[bn * HID + c];
    __syncthreads();
    float acc = 0.f;
#pragma unroll 16
    for (int h = 0; h < HID; ++h)
        acc += sh_inp[h] * weight[h * CH + c];
    g_nw[bn * CH + c] = acc;
    if (c < 32) {
        float s = 0.f;
#pragma unroll
        for (int i = 0; i < 4; ++i)
            s += sh_inp[c + 32 * i] * nfh[c + 32 * i];
#pragma unroll
        for (int o = 16; o; o >>= 1)
            s += __shfl_xor_sync(0xffffffffu, s, o);
        if (c == 0) g_n2[bn] = s;
    }
}

// ---------------------------------------------------------------------------
// Fused main kernel:
//   - 4 consecutive points per thread (all global traffic is 128-bit)
//   - 4-way channel split: quarter q handles channels [64q, 64q+64)
//   - f32x2 compute on point-pairs (p0,p1) and (p2,p3) w/ duplicated weights
//   - quarters exchange packed n1 partials via shared memory
// Grid: 512 blocks x 256 threads (131072 threads, block covers 256 points).
// ---------------------------------------------------------------------------
__global__ void __launch_bounds__(256, 3) main_kernel(
    const float* __restrict__ res,     // [2, 256, 65536]
    const float* __restrict__ Wres,    // [256, 7]
    float* __restrict__ out)           // [2, 256, 65536]
{
    __shared__ ull Wd[CH][8];                 // (w[c][n], w[c][n]) duplicated
    __shared__ ull NWd[CH][8];                // (nw[n][c], nw[n][c]) duplicated
    __shared__ ulonglong2 part[NODES][4][64]; // {(p0,p1),(p2,p3)} per quarter

    const int tid     = threadIdx.x;
    const int quarter = tid >> 6;        // 0..3  channel quarter
    const int pg      = tid & 63;        // point-group within block
    const int b       = blockIdx.x >> 8; // 0..1
    const int blk     = blockIdx.x & 255;
    const int pbase   = blk * 256 + pg * 4;   // first of this thread's 4 points

    // Stage duplicated weights: thread c handles channel c
    {
        const int c = tid;
#pragma unroll
        for (int n = 0; n < NODES; ++n) {
            float w = Wres[c * NODES + n];
            Wd[c][n] = pack2(w, w);
            float q = g_nw[(b * NODES + n) * CH + c];
            NWd[c][n] = pack2(q, q);
        }
        Wd[c][7]  = 0ull;
        NWd[c][7] = 0ull;
    }
    float n2s[NODES];
#pragma unroll
    for (int n = 0; n < NODES; ++n) n2s[n] = g_n2[b * NODES + n];
    __syncthreads();

    const int cbase = quarter * 64;
    const float4* rfp = (const float4*)(res + (size_t)b * CH * P_TOTAL)
                        + (size_t)cbase * P4 + (pbase >> 2);

    ull acc01[NODES], acc23[NODES];
#pragma unroll
    for (int n = 0; n < NODES; ++n) { acc01[n] = 0ull; acc23[n] = 0ull; }

    // ---- Pass 1: 64 channels x 4 points, LDG.128 per channel
    float4 buf[PF];
#pragma unroll
    for (int i = 0; i < PF; ++i)
        buf[i] = ldcs128(rfp + (size_t)i * P4);

#pragma unroll 1
    for (int jb = 0; jb < 64; jb += PF) {
#pragma unroll
        for (int i = 0; i < PF; ++i) {
            float4 v = buf[i];
            if (jb + PF < 64)
                buf[i] = ldcs128(rfp + (size_t)(jb + PF + i) * P4);
            ull v01 = pack2(v.x, v.y);
            ull v23 = pack2(v.z, v.w);
            const ulonglong2* wr = (const ulonglong2*)(&Wd[cbase + jb + i][0]);
            ulonglong2 w01 = wr[0];
            ulonglong2 w23 = wr[1];
            ulonglong2 w45 = wr[2];
            ulonglong2 w6p = wr[3];
            acc01[0] = fma2(v01, w01.x, acc01[0]);  acc23[0] = fma2(v23, w01.x, acc23[0]);
            acc01[1] = fma2(v01, w01.y, acc01[1]);  acc23[1] = fma2(v23, w01.y, acc23[1]);
            acc01[2] = fma2(v01, w23.x, acc01[2]);  acc23[2] = fma2(v23, w23.x, acc23[2]);
            acc01[3] = fma2(v01, w23.y, acc01[3]);  acc23[3] = fma2(v23, w23.y, acc23[3]);
            acc01[4] = fma2(v01, w45.x, acc01[4]);  acc23[4] = fma2(v23, w45.x, acc23[4]);
            acc01[5] = fma2(v01, w45.y, acc01[5]);  acc23[5] = fma2(v23, w45.y, acc23[5]);
            acc01[6] = fma2(v01, w6p.x, acc01[6]);  acc23[6] = fma2(v23, w6p.x, acc23[6]);
        }
    }

    // ---- Cross-quarter reduction of packed partials
#pragma unroll
    for (int n = 0; n < NODES; ++n)
        part[n][quarter][pg] = make_ulonglong2(acc01[n], acc23[n]);
    __syncthreads();

    ull s01[NODES], s23[NODES];
#pragma unroll
    for (int n = 0; n < NODES; ++n) {
        ull a = acc01[n], c2 = acc23[n];
#pragma unroll
        for (int q = 1; q < 4; ++q) {
            ulonglong2 t = part[n][(quarter + q) & 3][pg];
            a  = add2(a,  t.x);
            c2 = add2(c2, t.y);
        }
        s01[n] = a;
        s23[n] = c2;
    }

    // ---- Softmax over 7 nodes for 4 points
    float s0[NODES], s1[NODES], s2[NODES], s3[NODES];
#pragma unroll
    for (int n = 0; n < NODES; ++n) {
        float x, y;
        unpack2(s01[n], x, y);  s0[n] = x + n2s[n];  s1[n] = y + n2s[n];
        unpack2(s23[n], x, y);  s2[n] = x + n2s[n];  s3[n] = y + n2s[n];
    }
    float m0 = s0[0], m1 = s1[0], m2 = s2[0], m3 = s3[0];
#pragma unroll
    for (int n = 1; n < NODES; ++n) {
        m0 = fmaxf(m0, s0[n]); m1 = fmaxf(m1, s1[n]);
        m2 = fmaxf(m2, s2[n]); m3 = fmaxf(m3, s3[n]);
    }
    float t0 = 0.f, t1 = 0.f, t2 = 0.f, t3 = 0.f;
    float e0[NODES], e1[NODES], e2[NODES], e3[NODES];
#pragma unroll
    for (int n = 0; n < NODES; ++n) {
        e0[n] = __expf(s0[n] - m0); t0 += e0[n];
        e1[n] = __expf(s1[n] - m1); t1 += e1[n];
        e2[n] = __expf(s2[n] - m2); t2 += e2[n];
        e3[n] = __expf(s3[n] - m3); t3 += e3[n];
    }
    float i0 = __fdividef(1.f, t0);
    float i1 = __fdividef(1.f, t1);
    float i2 = __fdividef(1.f, t2);
    float i3 = __fdividef(1.f, t3);
    ull at01[NODES], at23[NODES];
#pragma unroll
    for (int n = 0; n < NODES; ++n) {
        at01[n] = pack2(e0[n] * i0, e1[n] * i1);
        at23[n] = pack2(e2[n] * i2, e3[n] * i3);
    }

    // ---- Pass 2: 64 channels x 4 points, STG.128 per channel
    float4* op = (float4*)(out + (size_t)b * CH * P_TOTAL)
                 + (size_t)cbase * P4 + (pbase >> 2);
#pragma unroll 4
    for (int j = 0; j < 64; ++j) {
        const ulonglong2* nr = (const ulonglong2*)(&NWd[cbase + j][0]);
        ulonglong2 q01 = nr[0];
        ulonglong2 q23 = nr[1];
        ulonglong2 q45 = nr[2];
        ulonglong2 q6p = nr[3];
        ull o01 = 0ull, o23 = 0ull;
        o01 = fma2(at01[0], q01.x, o01);  o23 = fma2(at23[0], q01.x, o23);
        o01 = fma2(at01[1], q01.y, o01);  o23 = fma2(at23[1], q01.y, o23);
        o01 = fma2(at01[2], q23.x, o01);  o23 = fma2(at23[2], q23.x, o23);
        o01 = fma2(at01[3], q23.y, o01);  o23 = fma2(at23[3], q23.y, o23);
        o01 = fma2(at01[4], q45.x, o01);  o23 = fma2(at23[4], q45.x, o23);
        o01 = fma2(at01[5], q45.y, o01);  o23 = fma2(at23[5], q45.y, o23);
        o01 = fma2(at01[6], q6p.x, o01);  o23 = fma2(at23[6], q6p.x, o23);
        float4 ov;
        unpack2(o01, ov.x, ov.y);
        unpack2(o23, ov.z, ov.w);
        ov.x = fmaxf(ov.x, 0.f);
        ov.y = fmaxf(ov.y, 0.f);
        ov.z = fmaxf(ov.z, 0.f);
        ov.w = fmaxf(ov.w, 0.f);
        stcs128(op + (size_t)j * P4, ov);
    }
}

// ---------------------------------------------------------------------------
extern "C" void kernel_launch(void* const* d_in, const int* in_sizes, int n_in,
                              void* d_out, int out_size) {
    const float* inp    = (const float*)d_in[0];  // [1,2,7,128]
    const float* res    = (const float*)d_in[1];  // [2,256,16,64,64]
    const float* Wres   = (const float*)d_in[2];  // [256,7]
    const float* nfh    = (const float*)d_in[3];  // [128,1]
    const float* weight = (const float*)d_in[4];  // [128,256]

    precompute_kernel<<<14, 256>>>(inp, nfh, weight);
    main_kernel<<<512, 256>>>(res, Wres, (float*)d_out);
}